// round 1
// baseline (speedup 1.0000x reference)
#include <cuda_runtime.h>

// Problem constants (fixed shapes)
#define NN 100000
#define EE 1600000
#define HIDD 128
#define OUTD 64

// ---------------- scratch (device globals: no allocation allowed) ------------
__device__ int   g_deg[NN];
__device__ int   g_off[NN];
__device__ int   g_cur[NN];
__device__ float g_dinv[NN];
__device__ int   g_srcs[EE];
__device__ int   g_bsum[256];
__device__ int   g_flag;            // nonzero => edge_index is int32
__device__ float g_uv[(size_t)NN * 256];   // per-row: [0:128)=u=A@Wl, [128:256)=v=A@Wr
__device__ float g_h1[(size_t)NN * 128];
__device__ float g_h [(size_t)NN * 128];

// ---------------- setup kernels ----------------------------------------------
__global__ void k_zero() {
    int i = blockIdx.x * blockDim.x + threadIdx.x;
    if (i < NN) g_deg[i] = 0;
    if (i == 0) g_flag = 0;
}

// int64 edge_index => every odd 32-bit word is 0 (values < 2^17).
// Sample 4096 odd words; any nonzero => int32 layout.
__global__ void k_detect(const unsigned int* __restrict__ w) {
    int i = blockIdx.x * blockDim.x + threadIdx.x;   // 0..4095
    unsigned v = w[2 * i + 1];
    if (v != 0u) g_flag = 1;
}

__device__ __forceinline__ int ld_edge(const void* ei, long long pos, int is64) {
    if (is64) return (int)((const long long*)ei)[pos];
    return ((const int*)ei)[pos];
}

__global__ void k_hist(const void* __restrict__ ei) {
    int e = blockIdx.x * blockDim.x + threadIdx.x;
    if (e >= EE) return;
    int is64 = (g_flag == 0);
    int d = ld_edge(ei, (long long)EE + e, is64);
    atomicAdd(&g_deg[d], 1);
}

__global__ void k_scan1() {
    __shared__ int sh[1024];
    int i = blockIdx.x * 1024 + threadIdx.x;
    int v = (i < NN) ? g_deg[i] : 0;
    sh[threadIdx.x] = v;
    __syncthreads();
    for (int d = 1; d < 1024; d <<= 1) {
        int t = (threadIdx.x >= d) ? sh[threadIdx.x - d] : 0;
        __syncthreads();
        sh[threadIdx.x] += t;
        __syncthreads();
    }
    if (i < NN) g_off[i] = sh[threadIdx.x] - v;      // exclusive within block
    if (threadIdx.x == 1023) g_bsum[blockIdx.x] = sh[1023];
}

__global__ void k_scan2() {
    // 98 block sums, serial
    int run = 0;
    const int NB = (NN + 1023) / 1024;
    for (int b = 0; b < NB; b++) {
        int t = g_bsum[b];
        g_bsum[b] = run;
        run += t;
    }
}

__global__ void k_scan3() {
    int i = blockIdx.x * 1024 + threadIdx.x;
    if (i >= NN) return;
    int o = g_off[i] + g_bsum[i >> 10];
    g_off[i] = o;
    g_cur[i] = o;
    int d = g_deg[i];
    g_dinv[i] = 1.0f / (float)(d > 1 ? d : 1);
}

__global__ void k_scatter(const void* __restrict__ ei) {
    int e = blockIdx.x * blockDim.x + threadIdx.x;
    if (e >= EE) return;
    int is64 = (g_flag == 0);
    int s = ld_edge(ei, (long long)e, is64);
    int d = ld_edge(ei, (long long)EE + e, is64);
    int p = atomicAdd(&g_cur[d], 1);
    g_srcs[p] = s;
}

// ---------------- dual GEMM: C[M x 256] = A[M x 128] @ [Wl | Wr] -------------
// block: 256 thr, 64 rows/block. Ws: 128x256 in smem (128KB), As: 64x128 (32KB).
__global__ void k_gemm_dual(const float* __restrict__ A,
                            const float* __restrict__ Wl,
                            const float* __restrict__ Wr,
                            float* __restrict__ C) {
    extern __shared__ float sm[];
    float* Ws = sm;             // [k*256 + c]
    float* As = sm + 128 * 256; // [r*128 + k]
    int tid = threadIdx.x;

    for (int t = tid; t < 128 * 32; t += 256) {
        int k = t >> 5, c4 = t & 31;
        ((float4*)(Ws + k * 256))[c4]       = ((const float4*)(Wl + k * 128))[c4];
        ((float4*)(Ws + k * 256 + 128))[c4] = ((const float4*)(Wr + k * 128))[c4];
    }
    int row0 = blockIdx.x * 64;
    for (int t = tid; t < 64 * 32; t += 256) {
        int r = t >> 5, k4 = t & 31;
        int row = row0 + r;
        float4 val = make_float4(0.f, 0.f, 0.f, 0.f);
        if (row < NN) val = ((const float4*)(A + (size_t)row * 128))[k4];
        ((float4*)(As + r * 128))[k4] = val;
    }
    __syncthreads();

    int ty = tid >> 5, tx = tid & 31;
    float acc[8][8];
#pragma unroll
    for (int i = 0; i < 8; i++)
#pragma unroll
        for (int j = 0; j < 8; j++) acc[i][j] = 0.f;

    for (int k = 0; k < 128; k++) {
        float a[8];
#pragma unroll
        for (int i = 0; i < 8; i++) a[i] = As[(ty * 8 + i) * 128 + k];
        float4 w0 = ((float4*)(Ws + k * 256))[tx * 2];
        float4 w1 = ((float4*)(Ws + k * 256))[tx * 2 + 1];
        float w[8] = {w0.x, w0.y, w0.z, w0.w, w1.x, w1.y, w1.z, w1.w};
#pragma unroll
        for (int i = 0; i < 8; i++)
#pragma unroll
            for (int j = 0; j < 8; j++) acc[i][j] = fmaf(a[i], w[j], acc[i][j]);
    }

#pragma unroll
    for (int i = 0; i < 8; i++) {
        int row = row0 + ty * 8 + i;
        if (row < NN) {
            float4 o0 = make_float4(acc[i][0], acc[i][1], acc[i][2], acc[i][3]);
            float4 o1 = make_float4(acc[i][4], acc[i][5], acc[i][6], acc[i][7]);
            float* cp = C + (size_t)row * 256 + tx * 8;
            ((float4*)cp)[0] = o0;
            ((float4*)cp)[1] = o1;
        }
    }
}

// ---------------- aggregation epilogue ---------------------------------------
// out[i] = relu( res[i] + dinv[i]*sum_{e in N(i)} u[src_e] + v[i] + bias )
// warp per node, lane covers 4 of the 128 features.
__global__ void k_agg(const float* __restrict__ uv,
                      const float* __restrict__ bias,
                      const float* __restrict__ res,   // may be null
                      float* __restrict__ out) {
    int node = blockIdx.x * 8 + (threadIdx.x >> 5);
    if (node >= NN) return;
    int lane = threadIdx.x & 31;
    int off = g_off[node];
    int d   = g_deg[node];

    float ax = 0.f, ay = 0.f, az = 0.f, aw = 0.f;
#pragma unroll 4
    for (int e = 0; e < d; e++) {
        int s = __ldg(&g_srcs[off + e]);
        float4 t = *(const float4*)(uv + (size_t)s * 256 + lane * 4);
        ax += t.x; ay += t.y; az += t.z; aw += t.w;
    }
    float di = g_dinv[node];
    float4 v = *(const float4*)(uv + (size_t)node * 256 + 128 + lane * 4);
    float4 b = *(const float4*)(bias + lane * 4);
    float rx = fmaf(ax, di, v.x + b.x);
    float ry = fmaf(ay, di, v.y + b.y);
    float rz = fmaf(az, di, v.z + b.z);
    float rw = fmaf(aw, di, v.w + b.w);
    if (res) {
        float4 h = *(const float4*)(res + (size_t)node * 128 + lane * 4);
        rx += h.x; ry += h.y; rz += h.z; rw += h.w;
    }
    rx = fmaxf(rx, 0.f); ry = fmaxf(ry, 0.f);
    rz = fmaxf(rz, 0.f); rw = fmaxf(rw, 0.f);
    *(float4*)(out + (size_t)node * 128 + lane * 4) = make_float4(rx, ry, rz, rw);
}

// ---------------- final GEMM: C[M x 64] = A[M x 128] @ Wlin + blin -----------
__global__ void k_gemm_final(const float* __restrict__ A,
                             const float* __restrict__ W,
                             const float* __restrict__ b,
                             float* __restrict__ C) {
    extern __shared__ float sm[];
    float* Ws = sm;            // [k*64 + c], 32KB
    float* As = sm + 128 * 64; // [r*128 + k], 32KB
    int tid = threadIdx.x;

    for (int t = tid; t < 128 * 16; t += 256) {
        int k = t >> 4, c4 = t & 15;
        ((float4*)(Ws + k * 64))[c4] = ((const float4*)(W + k * 64))[c4];
    }
    int row0 = blockIdx.x * 64;
    for (int t = tid; t < 64 * 32; t += 256) {
        int r = t >> 5, k4 = t & 31;
        int row = row0 + r;
        float4 val = make_float4(0.f, 0.f, 0.f, 0.f);
        if (row < NN) val = ((const float4*)(A + (size_t)row * 128))[k4];
        ((float4*)(As + r * 128))[k4] = val;
    }
    __syncthreads();

    int ty = tid >> 5, tx = tid & 31;
    float acc0[8], acc1[8];
#pragma unroll
    for (int i = 0; i < 8; i++) { acc0[i] = 0.f; acc1[i] = 0.f; }

    for (int k = 0; k < 128; k++) {
        float2 w = ((float2*)(Ws + k * 64))[tx];
#pragma unroll
        for (int i = 0; i < 8; i++) {
            float a = As[(ty * 8 + i) * 128 + k];
            acc0[i] = fmaf(a, w.x, acc0[i]);
            acc1[i] = fmaf(a, w.y, acc1[i]);
        }
    }
    float2 bl = ((const float2*)b)[tx];
#pragma unroll
    for (int i = 0; i < 8; i++) {
        int row = row0 + ty * 8 + i;
        if (row < NN) {
            float2 o = make_float2(acc0[i] + bl.x, acc1[i] + bl.y);
            ((float2*)(C + (size_t)row * 64 + tx * 2))[0] = o;
        }
    }
}

// ---------------- launch ------------------------------------------------------
extern "C" void kernel_launch(void* const* d_in, const int* in_sizes, int n_in,
                              void* d_out, int out_size) {
    const float* x    = (const float*)d_in[0];
    const void*  ei   = d_in[1];
    const float* W1l  = (const float*)d_in[2];
    const float* b1   = (const float*)d_in[3];
    const float* W1r  = (const float*)d_in[4];
    const float* W2l  = (const float*)d_in[5];
    const float* b2   = (const float*)d_in[6];
    const float* W2r  = (const float*)d_in[7];
    const float* Wlin = (const float*)d_in[8];
    const float* blin = (const float*)d_in[9];
    float* out = (float*)d_out;

    // idempotent attribute config (host-side, capture-safe)
    cudaFuncSetAttribute(k_gemm_dual,  cudaFuncAttributeMaxDynamicSharedMemorySize, 160 * 1024);
    cudaFuncSetAttribute(k_gemm_final, cudaFuncAttributeMaxDynamicSharedMemorySize, 64 * 1024);

    void *p_uv = nullptr, *p_h1 = nullptr, *p_h = nullptr;
    cudaGetSymbolAddress(&p_uv, g_uv);
    cudaGetSymbolAddress(&p_h1, g_h1);
    cudaGetSymbolAddress(&p_h,  g_h);
    float* uv = (float*)p_uv;
    float* h1 = (float*)p_h1;
    float* h  = (float*)p_h;

    const int NB_N   = (NN + 255) / 256;
    const int NB_E   = (EE + 255) / 256;
    const int NB_SC  = (NN + 1023) / 1024;
    const int NB_GE  = (NN + 63) / 64;
    const int NB_AGG = (NN + 7) / 8;
    const size_t SM_DUAL  = (size_t)(128 * 256 + 64 * 128) * 4; // 160KB
    const size_t SM_FINAL = (size_t)(128 * 64 + 64 * 128) * 4;  // 64KB

    // CSR build
    k_zero<<<NB_N, 256>>>();
    k_detect<<<16, 256>>>((const unsigned int*)ei);
    k_hist<<<NB_E, 256>>>(ei);
    k_scan1<<<NB_SC, 1024>>>();
    k_scan2<<<1, 1>>>();
    k_scan3<<<NB_SC, 1024>>>();
    k_scatter<<<NB_E, 256>>>(ei);

    // Layer 1: uv = x @ [W1l|W1r]; h1 = relu(mean_agg(u) + v + b1)
    k_gemm_dual<<<NB_GE, 256, SM_DUAL>>>(x, W1l, W1r, uv);
    k_agg<<<NB_AGG, 256>>>(uv, b1, nullptr, h1);

    // Layer 2: uv = h1 @ [W2l|W2r]; h = relu(h1 + mean_agg(u) + v + b2)
    k_gemm_dual<<<NB_GE, 256, SM_DUAL>>>(h1, W2l, W2r, uv);
    k_agg<<<NB_AGG, 256>>>(uv, b2, h1, h);

    // Head
    k_gemm_final<<<NB_GE, 256, SM_FINAL>>>(h, Wlin, blin, out);
}

// round 3
// speedup vs baseline: 1.6862x; 1.6862x over previous
#include <cuda_runtime.h>
#include <cuda_bf16.h>
#include <cstdint>

#define NN 100000
#define EE 1600000

// ---------------- scratch (device globals) -----------------------------------
__device__ int   g_deg[NN];
__device__ int   g_off[NN];
__device__ int   g_cur[NN];
__device__ float g_dinv[NN];
__device__ int   g_srcs[EE];
__device__ int   g_bsum[128];
__device__ int   g_flag;
__device__ float g_uv[(size_t)NN * 256];
__device__ float g_h1[(size_t)NN * 128];
__device__ float g_h [(size_t)NN * 128];
// pre-split, pre-swizzled weight images: Wt[n][k] bf16, row stride 256B, XOR swizzle
__device__ __align__(16) unsigned char g_w1hi[256 * 256];
__device__ __align__(16) unsigned char g_w1lo[256 * 256];
__device__ __align__(16) unsigned char g_w2hi[256 * 256];
__device__ __align__(16) unsigned char g_w2lo[256 * 256];
__device__ __align__(16) unsigned char g_wfhi[64 * 256];
__device__ __align__(16) unsigned char g_wflo[64 * 256];

// ---------------- helpers -----------------------------------------------------
__device__ __forceinline__ uint32_t smem_u32(const void* p) {
    uint32_t a;
    asm("{ .reg .u64 t; cvta.to.shared.u64 t, %1; cvt.u32.u64 %0, t; }" : "=r"(a) : "l"(p));
    return a;
}
// XOR swizzle for [rows x 128] bf16 tiles, 256B per row
__device__ __forceinline__ uint32_t swz(int row, int col) {
    uint32_t off = (uint32_t)row * 256u + (uint32_t)col * 2u;
    return off ^ (((uint32_t)row & 7u) << 4);
}
__device__ __forceinline__ void ldsm_x4(uint32_t* r, uint32_t addr) {
    asm volatile("ldmatrix.sync.aligned.m8n8.x4.shared.b16 {%0,%1,%2,%3}, [%4];"
                 : "=r"(r[0]), "=r"(r[1]), "=r"(r[2]), "=r"(r[3]) : "r"(addr));
}
__device__ __forceinline__ void mma_bf16(float* c, const uint32_t* a, const uint32_t* b) {
    asm volatile("mma.sync.aligned.m16n8k16.row.col.f32.bf16.bf16.f32 "
                 "{%0,%1,%2,%3}, {%4,%5,%6,%7}, {%8,%9}, {%0,%1,%2,%3};"
                 : "+f"(c[0]), "+f"(c[1]), "+f"(c[2]), "+f"(c[3])
                 : "r"(a[0]), "r"(a[1]), "r"(a[2]), "r"(a[3]), "r"(b[0]), "r"(b[1]));
}

// ---------------- CSR build ---------------------------------------------------
__global__ void k_zero() {
    int i = blockIdx.x * blockDim.x + threadIdx.x;
    if (i < NN) g_deg[i] = 0;
    if (i == 0) g_flag = 0;
}
__global__ void k_detect(const unsigned int* __restrict__ w) {
    int i = blockIdx.x * blockDim.x + threadIdx.x;
    if (w[2 * i + 1] != 0u) g_flag = 1;
}
__device__ __forceinline__ int ld_edge(const void* ei, long long pos, int is64) {
    if (is64) return (int)((const long long*)ei)[pos];
    return ((const int*)ei)[pos];
}
__global__ void k_hist(const void* __restrict__ ei) {
    int e = blockIdx.x * blockDim.x + threadIdx.x;
    if (e >= EE) return;
    int is64 = (g_flag == 0);
    atomicAdd(&g_deg[ld_edge(ei, (long long)EE + e, is64)], 1);
}
__global__ void k_scan1() {
    __shared__ int sh[1024];
    int i = blockIdx.x * 1024 + threadIdx.x;
    int v = (i < NN) ? g_deg[i] : 0;
    sh[threadIdx.x] = v;
    __syncthreads();
    for (int d = 1; d < 1024; d <<= 1) {
        int t = (threadIdx.x >= d) ? sh[threadIdx.x - d] : 0;
        __syncthreads();
        sh[threadIdx.x] += t;
        __syncthreads();
    }
    if (i < NN) g_off[i] = sh[threadIdx.x] - v;
    if (threadIdx.x == 1023) g_bsum[blockIdx.x] = sh[1023];
}
__global__ void k_scan2() {
    __shared__ int sh[128];
    int i = threadIdx.x;
    const int NB = (NN + 1023) / 1024;
    int v = (i < NB) ? g_bsum[i] : 0;
    sh[i] = v;
    __syncthreads();
    for (int d = 1; d < 128; d <<= 1) {
        int t = (i >= d) ? sh[i - d] : 0;
        __syncthreads();
        sh[i] += t;
        __syncthreads();
    }
    if (i < NB) g_bsum[i] = sh[i] - v;
}
__global__ void k_scan3() {
    int i = blockIdx.x * 1024 + threadIdx.x;
    if (i >= NN) return;
    int o = g_off[i] + g_bsum[i >> 10];
    g_off[i] = o;
    g_cur[i] = o;
    int d = g_deg[i];
    g_dinv[i] = 1.0f / (float)(d > 1 ? d : 1);
}
__global__ void k_scatter(const void* __restrict__ ei) {
    int e = blockIdx.x * blockDim.x + threadIdx.x;
    if (e >= EE) return;
    int is64 = (g_flag == 0);
    int s = ld_edge(ei, (long long)e, is64);
    int d = ld_edge(ei, (long long)EE + e, is64);
    g_srcs[atomicAdd(&g_cur[d], 1)] = s;
}

// ---------------- weight prep: Wt[n][k] bf16 hi/lo, swizzled ------------------
__global__ void k_prep_w(const float* __restrict__ W1l, const float* __restrict__ W1r,
                         const float* __restrict__ W2l, const float* __restrict__ W2r,
                         const float* __restrict__ Wlin) {
    int i = blockIdx.x * blockDim.x + threadIdx.x;
    float v;
    unsigned char *hi, *lo;
    uint32_t off;
    if (i < 65536) {
        int layer = i >> 15, e = i & 32767;
        int n = e >> 7, k = e & 127;
        const float* Wl = layer ? W2l : W1l;
        const float* Wr = layer ? W2r : W1r;
        v = (n < 128) ? Wl[k * 128 + n] : Wr[k * 128 + (n - 128)];
        hi = layer ? g_w2hi : g_w1hi;
        lo = layer ? g_w2lo : g_w1lo;
        off = swz(n, k);
    } else if (i < 65536 + 8192) {
        int e = i - 65536;
        int n = e >> 7, k = e & 127;
        v = Wlin[k * 64 + n];
        hi = g_wfhi; lo = g_wflo;
        off = swz(n, k);
    } else return;
    __nv_bfloat16 h = __float2bfloat16_rn(v);
    __nv_bfloat16 l = __float2bfloat16_rn(v - __bfloat162float(h));
    *(__nv_bfloat16*)(hi + off) = h;
    *(__nv_bfloat16*)(lo + off) = l;
}

// ---------------- mma.sync GEMM: C[128 x NC] = A[128x128] @ Wt^T --------------
// bf16x3 split: C = Ahi*Bhi + Ahi*Blo + Alo*Bhi (fp32 reg accumulation).
// 256 threads = 8 warps. Warp tile: 32(M) x NC/2(N).
template <int NC>
__global__ void __launch_bounds__(256, 1) k_gemm_mma(
    const float* __restrict__ A,
    const unsigned char* __restrict__ Bhi, const unsigned char* __restrict__ Blo,
    const float* __restrict__ bias,
    float* __restrict__ C) {
    extern __shared__ unsigned char sm[];
    const int BIAS = 0;
    const int AHI = 1024;
    const int ALO = AHI + 32768;
    const int BHI = ALO + 32768;
    const int BLO = BHI + NC * 256;
    uint32_t sb = smem_u32(sm);
    int tid = threadIdx.x, wid = tid >> 5, lane = tid & 31;

    // copy pre-swizzled weight images into SMEM
    const int BW = NC * 256 / 16;
    for (int i = tid; i < BW; i += 256) {
        ((float4*)(sm + BHI))[i] = ((const float4*)Bhi)[i];
        ((float4*)(sm + BLO))[i] = ((const float4*)Blo)[i];
    }
    if (bias) for (int i = tid; i < NC; i += 256) ((float*)(sm + BIAS))[i] = bias[i];

    // A convert: 2 threads per row, fp32 -> bf16 hi/lo into swizzled tiles
    int row0 = blockIdx.x * 128;
    {
        int r = tid >> 1, half = tid & 1;
        int row = row0 + r;
        const float* ap = A + (size_t)row * 128 + half * 64;
        for (int cc = 0; cc < 64; cc += 4) {
            float4 v = (row < NN) ? *(const float4*)(ap + cc)
                                  : make_float4(0.f, 0.f, 0.f, 0.f);
            __nv_bfloat16 hx = __float2bfloat16_rn(v.x), hy = __float2bfloat16_rn(v.y);
            __nv_bfloat16 hz = __float2bfloat16_rn(v.z), hw = __float2bfloat16_rn(v.w);
            __nv_bfloat162 h0, h1, l0, l1;
            h0.x = hx; h0.y = hy; h1.x = hz; h1.y = hw;
            l0.x = __float2bfloat16_rn(v.x - __bfloat162float(hx));
            l0.y = __float2bfloat16_rn(v.y - __bfloat162float(hy));
            l1.x = __float2bfloat16_rn(v.z - __bfloat162float(hz));
            l1.y = __float2bfloat16_rn(v.w - __bfloat162float(hw));
            uint32_t so = swz(r, half * 64 + cc);
            *(__nv_bfloat162*)(sm + AHI + so)     = h0;
            *(__nv_bfloat162*)(sm + AHI + so + 4) = h1;
            *(__nv_bfloat162*)(sm + ALO + so)     = l0;
            *(__nv_bfloat162*)(sm + ALO + so + 4) = l1;
        }
    }
    __syncthreads();

    const int WARP_N = NC / 2;
    const int NPAIRS = WARP_N / 16;       // 8 (dual) / 2 (final)
    const int NB8    = WARP_N / 8;
    int warp_m = (wid & 3) * 32;
    int warp_n = (wid >> 2) * WARP_N;

    float c[2][NB8][4];
#pragma unroll
    for (int mb = 0; mb < 2; mb++)
#pragma unroll
        for (int nb = 0; nb < NB8; nb++)
#pragma unroll
            for (int j = 0; j < 4; j++) c[mb][nb][j] = 0.f;

    // precompute lane-dependent row/col offsets
    int a_r = ((lane >> 3) & 1) * 8 + (lane & 7);   // + mb*16 + warp_m
    int a_c = (lane >> 4) * 8;                      // + k
    int b_r = (lane >> 4) * 8 + (lane & 7);         // + np*16 + warp_n
    int b_c = ((lane >> 3) & 1) * 8;                // + k

#pragma unroll
    for (int pass = 0; pass < 3; pass++) {
        uint32_t abase = sb + (pass == 2 ? ALO : AHI);
        uint32_t bbase = sb + (pass == 1 ? BLO : BHI);
#pragma unroll
        for (int k = 0; k < 128; k += 16) {
            uint32_t afr[2][4];
#pragma unroll
            for (int mb = 0; mb < 2; mb++)
                ldsm_x4(afr[mb], abase + swz(warp_m + mb * 16 + a_r, k + a_c));
#pragma unroll
            for (int np = 0; np < NPAIRS; np++) {
                uint32_t bfr[4];
                ldsm_x4(bfr, bbase + swz(warp_n + np * 16 + b_r, k + b_c));
#pragma unroll
                for (int mb = 0; mb < 2; mb++) {
                    mma_bf16(c[mb][np * 2],     afr[mb], bfr);
                    mma_bf16(c[mb][np * 2 + 1], afr[mb], bfr + 2);
                }
            }
        }
    }

    // epilogue: direct gmem write (float2 per fragment row)
    int g = lane >> 2, tg = lane & 3;
    const float* bs = (const float*)(sm + BIAS);
#pragma unroll
    for (int mb = 0; mb < 2; mb++) {
#pragma unroll
        for (int nb = 0; nb < NB8; nb++) {
            int col = warp_n + nb * 8 + tg * 2;
            float bx = 0.f, by = 0.f;
            if (bias) { bx = bs[col]; by = bs[col + 1]; }
            int r1 = row0 + warp_m + mb * 16 + g;
            if (r1 < NN)
                *(float2*)(C + (size_t)r1 * NC + col) =
                    make_float2(c[mb][nb][0] + bx, c[mb][nb][1] + by);
            int r2 = r1 + 8;
            if (r2 < NN)
                *(float2*)(C + (size_t)r2 * NC + col) =
                    make_float2(c[mb][nb][2] + bx, c[mb][nb][3] + by);
        }
    }
}

// ---------------- aggregation epilogue ---------------------------------------
__global__ void k_agg(const float* __restrict__ uv,
                      const float* __restrict__ bias,
                      const float* __restrict__ res,
                      float* __restrict__ out) {
    int node = blockIdx.x * 8 + (threadIdx.x >> 5);
    if (node >= NN) return;
    int lane = threadIdx.x & 31;
    int off = g_off[node];
    int d = g_deg[node];

    float ax = 0.f, ay = 0.f, az = 0.f, aw = 0.f;
#pragma unroll 4
    for (int e = 0; e < d; e++) {
        int s = __ldg(&g_srcs[off + e]);
        float4 t = *(const float4*)(uv + (size_t)s * 256 + lane * 4);
        ax += t.x; ay += t.y; az += t.z; aw += t.w;
    }
    float di = g_dinv[node];
    float4 v = *(const float4*)(uv + (size_t)node * 256 + 128 + lane * 4);
    float4 b = *(const float4*)(bias + lane * 4);
    float rx = fmaf(ax, di, v.x + b.x);
    float ry = fmaf(ay, di, v.y + b.y);
    float rz = fmaf(az, di, v.z + b.z);
    float rw = fmaf(aw, di, v.w + b.w);
    if (res) {
        float4 h = *(const float4*)(res + (size_t)node * 128 + lane * 4);
        rx += h.x; ry += h.y; rz += h.z; rw += h.w;
    }
    rx = fmaxf(rx, 0.f); ry = fmaxf(ry, 0.f);
    rz = fmaxf(rz, 0.f); rw = fmaxf(rw, 0.f);
    *(float4*)(out + (size_t)node * 128 + lane * 4) = make_float4(rx, ry, rz, rw);
}

// ---------------- launch ------------------------------------------------------
extern "C" void kernel_launch(void* const* d_in, const int* in_sizes, int n_in,
                              void* d_out, int out_size) {
    const float* x    = (const float*)d_in[0];
    const void*  ei   = d_in[1];
    const float* W1l  = (const float*)d_in[2];
    const float* b1   = (const float*)d_in[3];
    const float* W1r  = (const float*)d_in[4];
    const float* W2l  = (const float*)d_in[5];
    const float* b2   = (const float*)d_in[6];
    const float* W2r  = (const float*)d_in[7];
    const float* Wlin = (const float*)d_in[8];
    const float* blin = (const float*)d_in[9];
    float* out = (float*)d_out;

    const size_t SM_DUAL  = 1024 + 2 * 32768 + 2 * 256 * 256;  // 197632
    const size_t SM_FINAL = 1024 + 2 * 32768 + 2 * 64 * 256;   //  99328
    cudaFuncSetAttribute(k_gemm_mma<256>, cudaFuncAttributeMaxDynamicSharedMemorySize, (int)SM_DUAL);
    cudaFuncSetAttribute(k_gemm_mma<64>,  cudaFuncAttributeMaxDynamicSharedMemorySize, (int)SM_FINAL);

    void *p_uv, *p_h1, *p_h, *p_w1h, *p_w1l, *p_w2h, *p_w2l, *p_wfh, *p_wfl;
    cudaGetSymbolAddress(&p_uv, g_uv);
    cudaGetSymbolAddress(&p_h1, g_h1);
    cudaGetSymbolAddress(&p_h,  g_h);
    cudaGetSymbolAddress(&p_w1h, g_w1hi);
    cudaGetSymbolAddress(&p_w1l, g_w1lo);
    cudaGetSymbolAddress(&p_w2h, g_w2hi);
    cudaGetSymbolAddress(&p_w2l, g_w2lo);
    cudaGetSymbolAddress(&p_wfh, g_wfhi);
    cudaGetSymbolAddress(&p_wfl, g_wflo);
    float* uv = (float*)p_uv;
    float* h1 = (float*)p_h1;
    float* h  = (float*)p_h;

    const int NB_N   = (NN + 255) / 256;
    const int NB_E   = (EE + 255) / 256;
    const int NB_SC  = (NN + 1023) / 1024;
    const int NB_TC  = (NN + 127) / 128;
    const int NB_AGG = (NN + 7) / 8;

    // CSR build + weight prep
    k_zero<<<NB_N, 256>>>();
    k_detect<<<16, 256>>>((const unsigned int*)ei);
    k_prep_w<<<(73728 + 255) / 256, 256>>>(W1l, W1r, W2l, W2r, Wlin);
    k_hist<<<NB_E, 256>>>(ei);
    k_scan1<<<NB_SC, 1024>>>();
    k_scan2<<<1, 128>>>();
    k_scan3<<<NB_SC, 1024>>>();
    k_scatter<<<NB_E, 256>>>(ei);

    // Layer 1
    k_gemm_mma<256><<<NB_TC, 256, SM_DUAL>>>(x, (unsigned char*)p_w1h, (unsigned char*)p_w1l, nullptr, uv);
    k_agg<<<NB_AGG, 256>>>(uv, b1, nullptr, h1);
    // Layer 2
    k_gemm_mma<256><<<NB_TC, 256, SM_DUAL>>>(h1, (unsigned char*)p_w2h, (unsigned char*)p_w2l, nullptr, uv);
    k_agg<<<NB_AGG, 256>>>(uv, b2, h1, h);
    // Head
    k_gemm_mma<64><<<NB_TC, 256, SM_FINAL>>>(h, (unsigned char*)p_wfh, (unsigned char*)p_wfl, blin, out);
}